// round 2
// baseline (speedup 1.0000x reference)
#include <cuda_runtime.h>
#include <math.h>

#ifndef M_PI
#define M_PI 3.14159265358979323846
#endif

namespace {

constexpr int NP = 6;      // particles
constexpr int NBASE = 64;  // basis functions
constexpr int NWARP = 8;   // warps per block
constexpr int NTHR = NWARP * 32;

// pair (i<j) index tables, t = 0..14
__constant__ int c_PI[16] = {0,0,0,0,0,1,1,1,1,2,2,2,3,3,4,0};
__constant__ int c_PJ[16] = {1,2,3,4,5,2,3,4,5,3,4,5,4,5,5,1};

struct __align__(16) Smem {
  float2 F2[3][NBASE][32];   // [m][k][l] = (F_m[k][l], F_m[k][l+32]); m: 0=uu_a,1=dd_a,2=ud
  float4 W1t[32];            // [o] = (W1[0][o],W1[1][o],W1[2][o],W1[3][o])
  float4 W2t[32][8];         // [o][q] = (W2[4q][o],...,W2[4q+3][o])
  float  phi[NWARP][NP][NBASE];
  float  gs [NWARP][NP][NBASE];  // Phi_p @ F_same(spin_p)
  float  gu [NWARP][NP][NBASE];  // Phi_p @ F_ud (valid only for up particles)
  float  b1[32];
  float  b2[32];
  float  W3s[32];
  float  xs[NWARP][NP][2];
  int    sp[NWARP][NP];
  float  afin[NWARP][16];
  float  b3s, scale_s;
};

__device__ __forceinline__ float silu_f(float x) {
  // silu(x) = x * sigmoid(x) = 0.5*x*(1 + tanh(x/2)); single MUFU op
  float t;
  asm("tanh.approx.f32 %0, %1;" : "=f"(t) : "f"(x * 0.5f));
  return 0.5f * x * (1.0f + t);
}

// G[c] = sum_k phi[k] * F[k][c] for c = lane, lane+32
__device__ __forceinline__ float2 gemv64(const float2* __restrict__ Fl,
                                         const float* __restrict__ ph) {
  float a0 = 0.f, a1 = 0.f, b0 = 0.f, b1 = 0.f;
#pragma unroll
  for (int k = 0; k < NBASE; k += 4) {
    float4 p = *reinterpret_cast<const float4*>(ph + k);
    float2 f0 = Fl[(k + 0) * 32];
    float2 f1 = Fl[(k + 1) * 32];
    float2 f2 = Fl[(k + 2) * 32];
    float2 f3 = Fl[(k + 3) * 32];
    a0 = fmaf(p.x, f0.x, a0); a1 = fmaf(p.x, f0.y, a1);
    b0 = fmaf(p.y, f1.x, b0); b1 = fmaf(p.y, f1.y, b1);
    a0 = fmaf(p.z, f2.x, a0); a1 = fmaf(p.z, f2.y, a1);
    b0 = fmaf(p.w, f3.x, b0); b1 = fmaf(p.w, f3.y, b1);
  }
  return make_float2(a0 + b0, a1 + b1);
}

__global__ void __launch_bounds__(NTHR, 2)
pfaffian_kernel(const float* __restrict__ x, const int* __restrict__ spin,
                const float* __restrict__ F_ud, const float* __restrict__ F_uu,
                const float* __restrict__ F_dd,
                const float* __restrict__ W1, const float* __restrict__ b1,
                const float* __restrict__ W2, const float* __restrict__ b2,
                const float* __restrict__ W3, const float* __restrict__ b3,
                const float* __restrict__ scale,
                float* __restrict__ out, int Bt) {
  extern __shared__ char smem_raw[];
  Smem* S = reinterpret_cast<Smem*>(smem_raw);
  const int tid = threadIdx.x;
  const int w = tid >> 5, lane = tid & 31;

  // ---------- stage static data into smem ----------
  for (int idx = tid; idx < 3 * NBASE * 32; idx += NTHR) {
    int m = idx >> 11, r = idx & 2047, k = r >> 5, l = r & 31;
    float a, b;
    if (m == 2) {
      a = F_ud[k * 64 + l];
      b = F_ud[k * 64 + l + 32];
    } else {
      const float* F = m ? F_dd : F_uu;
      a = F[k * 64 + l]      - F[l * 64 + k];         // antisymmetrize
      b = F[k * 64 + l + 32] - F[(l + 32) * 64 + k];
    }
    S->F2[m][k][l] = make_float2(a, b);
  }
  if (tid < 32) {
    int o = tid;
    S->W1t[o] = make_float4(W1[o], W1[32 + o], W1[64 + o], W1[96 + o]);
    S->b1[o] = b1[o]; S->b2[o] = b2[o]; S->W3s[o] = W3[o];
  }
  for (int idx = tid; idx < 32 * 8; idx += NTHR) {
    int o = idx >> 3, q = idx & 7;
    S->W2t[o][q] = make_float4(W2[(4 * q + 0) * 32 + o], W2[(4 * q + 1) * 32 + o],
                               W2[(4 * q + 2) * 32 + o], W2[(4 * q + 3) * 32 + o]);
  }
  if (tid == 0) { S->b3s = b3[0]; S->scale_s = scale[0]; }
  __syncthreads();

  // ---------- per-lane basis constants ----------
  // lane owns basis columns c1 = lane (nx=lane>>3, ny=lane&7) and c2 = lane+32 (nx+4, ny)
  const int nx1 = lane >> 3, nyi = lane & 7;
  float nA = 0.f, nB = 0.f, nC = 0.f;
  {
    double spi = sqrt(M_PI);
    double d = 1.0;  // 2^m * m!
    for (int m2 = 0; m2 < 8; m2++) {
      float v = (float)(1.0 / sqrt(d * spi));
      if (m2 == nx1) nA = v;
      if (m2 == nx1 + 4) nB = v;
      if (m2 == nyi) nC = v;
      d *= 2.0 * (m2 + 1);
    }
  }
  const float norm1 = nA * nC, norm2 = nB * nC;

  const int ngroups = (Bt + NWARP - 1) / NWARP;
  for (int g = blockIdx.x; g < ngroups; g += gridDim.x) {
    const int e = g * NWARP + w;
    if (e >= Bt) continue;

    // ---- load x, spin for this element ----
    if (lane < NP) {
      float2 xv = *reinterpret_cast<const float2*>(x + (size_t)e * NP * 2 + lane * 2);
      S->xs[w][lane][0] = xv.x;
      S->xs[w][lane][1] = xv.y;
      S->sp[w][lane] = spin[(size_t)e * NP + lane];
    }
    __syncwarp();

    // ---- basis Phi ----
#pragma unroll
    for (int p = 0; p < NP; p++) {
      float u = S->xs[w][p][0], v = S->xs[w][p][1];
      // Hermite(u): pick degrees nx1 and nx1+4
      float hm = 1.f, h = 2.f * u;
      float hxa = (nx1 == 0) ? 1.f : h;  // nx1 in 0..3; >=2 overwritten below
      float hxb = h;                      // nx1+4 in 4..7; always overwritten
#pragma unroll
      for (int k = 2; k < 8; k++) {
        float hn = fmaf(2.f * u, h, -2.f * (float)(k - 1) * hm);
        hm = h; h = hn;
        if (nx1 == k) hxa = hn;
        if (nx1 + 4 == k) hxb = hn;
      }
      // Hermite(v): pick degree nyi
      float gm = 1.f, gh = 2.f * v;
      float hy = (nyi == 0) ? 1.f : gh;
#pragma unroll
      for (int k = 2; k < 8; k++) {
        float gn = fmaf(2.f * v, gh, -2.f * (float)(k - 1) * gm);
        gm = gh; gh = gn;
        if (nyi == k) hy = gn;
      }
      float gexp = __expf(-0.5f * (u * u + v * v));
      S->phi[w][p][lane]      = hxa * hy * (norm1 * gexp);
      S->phi[w][p][lane + 32] = hxb * hy * (norm2 * gexp);
    }
    __syncwarp();

    // ---- spin-aware GEMVs: G_same always, G_ud only for up particles ----
#pragma unroll 2
    for (int p = 0; p < NP; p++) {
      int spp = S->sp[w][p];  // warp-uniform
      const float* ph = S->phi[w][p];
      float2 g2 = gemv64(&S->F2[spp ? 1 : 0][0][lane], ph);
      S->gs[w][p][lane] = g2.x;
      S->gs[w][p][lane + 32] = g2.y;
      if (spp == 0) {
        float2 u2 = gemv64(&S->F2[2][0][lane], ph);
        S->gu[w][p][lane] = u2.x;
        S->gu[w][p][lane + 32] = u2.y;
      }
    }
    __syncwarp();

    // ---- A base entries for 15 upper-tri pairs ----
    float abase = 0.f;
    {
      int spl[NP];
#pragma unroll
      for (int p = 0; p < NP; p++) spl[p] = S->sp[w][p];
      constexpr int PIc[15] = {0,0,0,0,0,1,1,1,1,2,2,2,3,3,4};
      constexpr int PJc[15] = {1,2,3,4,5,2,3,4,5,3,4,5,4,5,5};
#pragma unroll
      for (int t = 0; t < 15; t++) {
        const int i = PIc[t], j = PJc[t];
        int si = spl[i], sj = spl[j];
        bool swapd = (si == 1) && (sj == 0);  // (down, up): use -A_ud[j][i]
        int ii = swapd ? j : i;
        int jj = swapd ? i : j;
        const float* buf = (si == sj) ? S->gs[w][ii] : S->gu[w][ii];
        const float* pj = S->phi[w][jj];
        float val = fmaf(buf[lane], pj[lane], buf[lane + 32] * pj[lane + 32]);
#pragma unroll
        for (int off = 16; off; off >>= 1)
          val += __shfl_xor_sync(0xffffffffu, val, off);
        if (swapd) val = -val;
        if (lane == t) abase = val;
      }
    }

    // ---- pair-correction MLP: lanes 0..14 -> (i,j), lanes 16..30 -> (j,i) ----
    {
      int t = lane & 15;  // t==15 maps to pair 0 via table slot 15 (dummy)
      bool rev = lane >= 16;
      int pi = c_PI[t], pj_ = c_PJ[t];
      int i = rev ? pj_ : pi;
      int j = rev ? pi : pj_;
      float f0 = S->xs[w][i][0] - S->xs[w][j][0];
      float f1 = S->xs[w][i][1] - S->xs[w][j][1];
      float f2v = f0 * f0 + f1 * f1;
      float f3 = (S->sp[w][i] == S->sp[w][j]) ? 1.f : 0.f;

      float h1r[32];
#pragma unroll
      for (int o = 0; o < 32; o++) {
        float4 w4 = S->W1t[o];
        float acc = fmaf(f0, w4.x, fmaf(f1, w4.y, fmaf(f2v, w4.z, fmaf(f3, w4.w, S->b1[o]))));
        h1r[o] = silu_f(acc);
      }
      float outv = S->b3s;
#pragma unroll 4
      for (int o = 0; o < 32; o++) {
        float acc = S->b2[o];
#pragma unroll
        for (int q = 0; q < 8; q++) {
          float4 w4 = S->W2t[o][q];
          acc = fmaf(h1r[4 * q], w4.x,
                fmaf(h1r[4 * q + 1], w4.y,
                fmaf(h1r[4 * q + 2], w4.z,
                fmaf(h1r[4 * q + 3], w4.w, acc))));
        }
        outv = fmaf(silu_f(acc), S->W3s[o], outv);
      }
      float orev = __shfl_down_sync(0xffffffffu, outv, 16);
      if (lane < 15) S->afin[w][lane] = abase + S->scale_s * (outv - orev);
    }
    __syncwarp();

    // ---- Pfaffian (lane 0) ----
    if (lane == 0) {
      const float* a = S->afin[w];
      float a0 = a[0], a1 = a[1], a2 = a[2], a3 = a[3], a4 = a[4];
      float a5 = a[5], a6 = a[6], a7 = a[7], a8 = a[8], a9 = a[9];
      float a10 = a[10], a11 = a[11], a12 = a[12], a13 = a[13], a14 = a[14];
      float pf = a0 * (a9 * a14 - a10 * a13 + a11 * a12)
               - a1 * (a6 * a14 - a7 * a13 + a8 * a12)
               + a2 * (a5 * a14 - a7 * a11 + a8 * a10)
               - a3 * (a5 * a13 - a6 * a11 + a8 * a9)
               + a4 * (a5 * a12 - a6 * a10 + a7 * a9);
      float sgn = (pf == 0.f) ? 1.f : ((pf > 0.f) ? 1.f : -1.f);
      float la = 0.5f * __logf(pf * pf);  // ref adds 1e-60 which is 0 in f32
      out[e] = sgn;
      out[Bt + e] = la;
    }
    __syncwarp();
  }
}

}  // namespace

extern "C" void kernel_launch(void* const* d_in, const int* in_sizes, int n_in,
                              void* d_out, int out_size) {
  const float* x     = (const float*)d_in[0];
  const int*   spin  = (const int*)d_in[1];
  const float* F_ud  = (const float*)d_in[2];
  const float* F_uu  = (const float*)d_in[3];
  const float* F_dd  = (const float*)d_in[4];
  const float* W1    = (const float*)d_in[5];
  const float* b1    = (const float*)d_in[6];
  const float* W2    = (const float*)d_in[7];
  const float* b2    = (const float*)d_in[8];
  const float* W3    = (const float*)d_in[9];
  const float* b3    = (const float*)d_in[10];
  const float* scale = (const float*)d_in[11];
  float* out = (float*)d_out;

  const int Bt = in_sizes[0] / (NP * 2);
  const int smem = (int)sizeof(Smem);

  cudaFuncSetAttribute(pfaffian_kernel, cudaFuncAttributeMaxDynamicSharedMemorySize, smem);

  int dev = 0;
  cudaGetDevice(&dev);
  int nsm = 148;
  cudaDeviceGetAttribute(&nsm, cudaDevAttrMultiProcessorCount, dev);

  const int ngroups = (Bt + NWARP - 1) / NWARP;
  int grid = nsm * 2;
  if (grid > ngroups) grid = ngroups;

  pfaffian_kernel<<<grid, NTHR, smem>>>(x, spin, F_ud, F_uu, F_dd,
                                        W1, b1, W2, b2, W3, b3, scale, out, Bt);
}

// round 3
// speedup vs baseline: 1.0004x; 1.0004x over previous
#include <cuda_runtime.h>
#include <math.h>

#ifndef M_PI
#define M_PI 3.14159265358979323846
#endif

namespace {

constexpr int NP = 6;      // particles
constexpr int NBASE = 64;  // basis functions
constexpr int NWARP = 8;   // warps per block
constexpr int NTHR = NWARP * 32;

// pair (i<j) index tables, t = 0..14
__constant__ int c_PI[16] = {0,0,0,0,0,1,1,1,1,2,2,2,3,3,4,0};
__constant__ int c_PJ[16] = {1,2,3,4,5,2,3,4,5,3,4,5,4,5,5,1};

struct __align__(16) Smem {
  float2 F2[3][NBASE][32];   // [m][k][l] = (F_m[k][l], F_m[k][l+32]); m: 0=uu_a,1=dd_a,2=ud
  float4 W1t[32];            // [o] = (W1[0][o],W1[1][o],W1[2][o],W1[3][o])
  float4 W2t[32][8];         // [o][q] = (W2[4q][o],...,W2[4q+3][o])
  float  phi[NWARP][NP][NBASE];
  float  gs [NWARP][NP][NBASE];  // Phi_p @ F_same(spin_p)
  float  gu [NWARP][NP][NBASE];  // Phi_p @ F_ud (valid only for up particles)
  float  b1[32];
  float  b2[32];
  float  W3s[32];
  float  xs[NWARP][NP][2];
  int    sp[NWARP][NP];
  float  afin[NWARP][16];
  float  b3s, scale_s;
};

__device__ __forceinline__ float silu_f(float x) {
  // silu(x) = x * sigmoid(x) = 0.5*x*(1 + tanh(x/2)); single MUFU op
  float t;
  asm("tanh.approx.f32 %0, %1;" : "=f"(t) : "f"(x * 0.5f));
  return 0.5f * x * (1.0f + t);
}

// G[c] = sum_k phi[k] * F[k][c] for c = lane, lane+32
__device__ __forceinline__ float2 gemv64(const float2* __restrict__ Fl,
                                         const float* __restrict__ ph) {
  float a0 = 0.f, a1 = 0.f, b0 = 0.f, b1 = 0.f;
#pragma unroll
  for (int k = 0; k < NBASE; k += 4) {
    float4 p = *reinterpret_cast<const float4*>(ph + k);
    float2 f0 = Fl[(k + 0) * 32];
    float2 f1 = Fl[(k + 1) * 32];
    float2 f2 = Fl[(k + 2) * 32];
    float2 f3 = Fl[(k + 3) * 32];
    a0 = fmaf(p.x, f0.x, a0); a1 = fmaf(p.x, f0.y, a1);
    b0 = fmaf(p.y, f1.x, b0); b1 = fmaf(p.y, f1.y, b1);
    a0 = fmaf(p.z, f2.x, a0); a1 = fmaf(p.z, f2.y, a1);
    b0 = fmaf(p.w, f3.x, b0); b1 = fmaf(p.w, f3.y, b1);
  }
  return make_float2(a0 + b0, a1 + b1);
}

__global__ void __launch_bounds__(NTHR, 2)
pfaffian_kernel(const float* __restrict__ x, const int* __restrict__ spin,
                const float* __restrict__ F_ud, const float* __restrict__ F_uu,
                const float* __restrict__ F_dd,
                const float* __restrict__ W1, const float* __restrict__ b1,
                const float* __restrict__ W2, const float* __restrict__ b2,
                const float* __restrict__ W3, const float* __restrict__ b3,
                const float* __restrict__ scale,
                float* __restrict__ out, int Bt) {
  extern __shared__ char smem_raw[];
  Smem* S = reinterpret_cast<Smem*>(smem_raw);
  const int tid = threadIdx.x;
  const int w = tid >> 5, lane = tid & 31;

  // ---------- stage static data into smem ----------
  for (int idx = tid; idx < 3 * NBASE * 32; idx += NTHR) {
    int m = idx >> 11, r = idx & 2047, k = r >> 5, l = r & 31;
    float a, b;
    if (m == 2) {
      a = F_ud[k * 64 + l];
      b = F_ud[k * 64 + l + 32];
    } else {
      const float* F = m ? F_dd : F_uu;
      a = F[k * 64 + l]      - F[l * 64 + k];         // antisymmetrize
      b = F[k * 64 + l + 32] - F[(l + 32) * 64 + k];
    }
    S->F2[m][k][l] = make_float2(a, b);
  }
  if (tid < 32) {
    int o = tid;
    S->W1t[o] = make_float4(W1[o], W1[32 + o], W1[64 + o], W1[96 + o]);
    S->b1[o] = b1[o]; S->b2[o] = b2[o]; S->W3s[o] = W3[o];
  }
  for (int idx = tid; idx < 32 * 8; idx += NTHR) {
    int o = idx >> 3, q = idx & 7;
    S->W2t[o][q] = make_float4(W2[(4 * q + 0) * 32 + o], W2[(4 * q + 1) * 32 + o],
                               W2[(4 * q + 2) * 32 + o], W2[(4 * q + 3) * 32 + o]);
  }
  if (tid == 0) { S->b3s = b3[0]; S->scale_s = scale[0]; }
  __syncthreads();

  // ---------- per-lane basis constants ----------
  // lane owns basis columns c1 = lane (nx=lane>>3, ny=lane&7) and c2 = lane+32 (nx+4, ny)
  const int nx1 = lane >> 3, nyi = lane & 7;
  float nA = 0.f, nB = 0.f, nC = 0.f;
  {
    double spi = sqrt(M_PI);
    double d = 1.0;  // 2^m * m!
    for (int m2 = 0; m2 < 8; m2++) {
      float v = (float)(1.0 / sqrt(d * spi));
      if (m2 == nx1) nA = v;
      if (m2 == nx1 + 4) nB = v;
      if (m2 == nyi) nC = v;
      d *= 2.0 * (m2 + 1);
    }
  }
  const float norm1 = nA * nC, norm2 = nB * nC;

  const int ngroups = (Bt + NWARP - 1) / NWARP;
  for (int g = blockIdx.x; g < ngroups; g += gridDim.x) {
    const int e = g * NWARP + w;
    if (e >= Bt) continue;

    // ---- load x, spin for this element ----
    if (lane < NP) {
      float2 xv = *reinterpret_cast<const float2*>(x + (size_t)e * NP * 2 + lane * 2);
      S->xs[w][lane][0] = xv.x;
      S->xs[w][lane][1] = xv.y;
      S->sp[w][lane] = spin[(size_t)e * NP + lane];
    }
    __syncwarp();

    // ---- basis Phi ----
#pragma unroll
    for (int p = 0; p < NP; p++) {
      float u = S->xs[w][p][0], v = S->xs[w][p][1];
      // Hermite(u): pick degrees nx1 and nx1+4
      float hm = 1.f, h = 2.f * u;
      float hxa = (nx1 == 0) ? 1.f : h;  // nx1 in 0..3; >=2 overwritten below
      float hxb = h;                      // nx1+4 in 4..7; always overwritten
#pragma unroll
      for (int k = 2; k < 8; k++) {
        float hn = fmaf(2.f * u, h, -2.f * (float)(k - 1) * hm);
        hm = h; h = hn;
        if (nx1 == k) hxa = hn;
        if (nx1 + 4 == k) hxb = hn;
      }
      // Hermite(v): pick degree nyi
      float gm = 1.f, gh = 2.f * v;
      float hy = (nyi == 0) ? 1.f : gh;
#pragma unroll
      for (int k = 2; k < 8; k++) {
        float gn = fmaf(2.f * v, gh, -2.f * (float)(k - 1) * gm);
        gm = gh; gh = gn;
        if (nyi == k) hy = gn;
      }
      float gexp = __expf(-0.5f * (u * u + v * v));
      S->phi[w][p][lane]      = hxa * hy * (norm1 * gexp);
      S->phi[w][p][lane + 32] = hxb * hy * (norm2 * gexp);
    }
    __syncwarp();

    // ---- spin-aware GEMVs: G_same always, G_ud only for up particles ----
#pragma unroll 2
    for (int p = 0; p < NP; p++) {
      int spp = S->sp[w][p];  // warp-uniform
      const float* ph = S->phi[w][p];
      float2 g2 = gemv64(&S->F2[spp ? 1 : 0][0][lane], ph);
      S->gs[w][p][lane] = g2.x;
      S->gs[w][p][lane + 32] = g2.y;
      if (spp == 0) {
        float2 u2 = gemv64(&S->F2[2][0][lane], ph);
        S->gu[w][p][lane] = u2.x;
        S->gu[w][p][lane + 32] = u2.y;
      }
    }
    __syncwarp();

    // ---- A base entries for 15 upper-tri pairs ----
    float abase = 0.f;
    {
      int spl[NP];
#pragma unroll
      for (int p = 0; p < NP; p++) spl[p] = S->sp[w][p];
      constexpr int PIc[15] = {0,0,0,0,0,1,1,1,1,2,2,2,3,3,4};
      constexpr int PJc[15] = {1,2,3,4,5,2,3,4,5,3,4,5,4,5,5};
#pragma unroll
      for (int t = 0; t < 15; t++) {
        const int i = PIc[t], j = PJc[t];
        int si = spl[i], sj = spl[j];
        bool swapd = (si == 1) && (sj == 0);  // (down, up): use -A_ud[j][i]
        int ii = swapd ? j : i;
        int jj = swapd ? i : j;
        const float* buf = (si == sj) ? S->gs[w][ii] : S->gu[w][ii];
        const float* pj = S->phi[w][jj];
        float val = fmaf(buf[lane], pj[lane], buf[lane + 32] * pj[lane + 32]);
#pragma unroll
        for (int off = 16; off; off >>= 1)
          val += __shfl_xor_sync(0xffffffffu, val, off);
        if (swapd) val = -val;
        if (lane == t) abase = val;
      }
    }

    // ---- pair-correction MLP: lanes 0..14 -> (i,j), lanes 16..30 -> (j,i) ----
    {
      int t = lane & 15;  // t==15 maps to pair 0 via table slot 15 (dummy)
      bool rev = lane >= 16;
      int pi = c_PI[t], pj_ = c_PJ[t];
      int i = rev ? pj_ : pi;
      int j = rev ? pi : pj_;
      float f0 = S->xs[w][i][0] - S->xs[w][j][0];
      float f1 = S->xs[w][i][1] - S->xs[w][j][1];
      float f2v = f0 * f0 + f1 * f1;
      float f3 = (S->sp[w][i] == S->sp[w][j]) ? 1.f : 0.f;

      float h1r[32];
#pragma unroll
      for (int o = 0; o < 32; o++) {
        float4 w4 = S->W1t[o];
        float acc = fmaf(f0, w4.x, fmaf(f1, w4.y, fmaf(f2v, w4.z, fmaf(f3, w4.w, S->b1[o]))));
        h1r[o] = silu_f(acc);
      }
      float outv = S->b3s;
#pragma unroll 4
      for (int o = 0; o < 32; o++) {
        float acc = S->b2[o];
#pragma unroll
        for (int q = 0; q < 8; q++) {
          float4 w4 = S->W2t[o][q];
          acc = fmaf(h1r[4 * q], w4.x,
                fmaf(h1r[4 * q + 1], w4.y,
                fmaf(h1r[4 * q + 2], w4.z,
                fmaf(h1r[4 * q + 3], w4.w, acc))));
        }
        outv = fmaf(silu_f(acc), S->W3s[o], outv);
      }
      float orev = __shfl_down_sync(0xffffffffu, outv, 16);
      if (lane < 15) S->afin[w][lane] = abase + S->scale_s * (outv - orev);
    }
    __syncwarp();

    // ---- Pfaffian (lane 0) ----
    if (lane == 0) {
      const float* a = S->afin[w];
      float a0 = a[0], a1 = a[1], a2 = a[2], a3 = a[3], a4 = a[4];
      float a5 = a[5], a6 = a[6], a7 = a[7], a8 = a[8], a9 = a[9];
      float a10 = a[10], a11 = a[11], a12 = a[12], a13 = a[13], a14 = a[14];
      float pf = a0 * (a9 * a14 - a10 * a13 + a11 * a12)
               - a1 * (a6 * a14 - a7 * a13 + a8 * a12)
               + a2 * (a5 * a14 - a7 * a11 + a8 * a10)
               - a3 * (a5 * a13 - a6 * a11 + a8 * a9)
               + a4 * (a5 * a12 - a6 * a10 + a7 * a9);
      float sgn = (pf == 0.f) ? 1.f : ((pf > 0.f) ? 1.f : -1.f);
      float la = 0.5f * __logf(pf * pf);  // ref adds 1e-60 which is 0 in f32
      out[e] = sgn;
      out[Bt + e] = la;
    }
    __syncwarp();
  }
}

}  // namespace

extern "C" void kernel_launch(void* const* d_in, const int* in_sizes, int n_in,
                              void* d_out, int out_size) {
  const float* x     = (const float*)d_in[0];
  const int*   spin  = (const int*)d_in[1];
  const float* F_ud  = (const float*)d_in[2];
  const float* F_uu  = (const float*)d_in[3];
  const float* F_dd  = (const float*)d_in[4];
  const float* W1    = (const float*)d_in[5];
  const float* b1    = (const float*)d_in[6];
  const float* W2    = (const float*)d_in[7];
  const float* b2    = (const float*)d_in[8];
  const float* W3    = (const float*)d_in[9];
  const float* b3    = (const float*)d_in[10];
  const float* scale = (const float*)d_in[11];
  float* out = (float*)d_out;

  const int Bt = in_sizes[0] / (NP * 2);
  const int smem = (int)sizeof(Smem);

  cudaFuncSetAttribute(pfaffian_kernel, cudaFuncAttributeMaxDynamicSharedMemorySize, smem);

  int dev = 0;
  cudaGetDevice(&dev);
  int nsm = 148;
  cudaDeviceGetAttribute(&nsm, cudaDevAttrMultiProcessorCount, dev);

  const int ngroups = (Bt + NWARP - 1) / NWARP;
  int grid = nsm * 2;
  if (grid > ngroups) grid = ngroups;

  pfaffian_kernel<<<grid, NTHR, smem>>>(x, spin, F_ud, F_uu, F_dd,
                                        W1, b1, W2, b2, W3, b3, scale, out, Bt);
}

// round 4
// speedup vs baseline: 1.4506x; 1.4499x over previous
#include <cuda_runtime.h>
#include <math.h>

#ifndef M_PI
#define M_PI 3.14159265358979323846
#endif

namespace {

constexpr int NP = 6;
constexpr int NWARP = 8;
constexpr int NTHR = NWARP * 32;

// pair index tables packed as nibbles: entry t at bits [4t,4t+4)
__device__ constexpr unsigned long long CI_PACK = 0x0433222111100000ull;
__device__ constexpr unsigned long long CJ_PACK = 0x0554543543254321ull;

typedef unsigned long long u64;

struct __align__(16) Smem {
  float4 F4[3][32][32];       // [m][k2][l] = (F[2k2][l], F[2k2][l+32], F[2k2+1][l], F[2k2+1][l+32])
  float  phis[NWARP][NP][64]; // scalar phi per warp
  float4 W1t[32];             // (W1[0][o],W1[1][o],W1[2][o],W1[3][o])
  float4 W2t[32][8];          // (W2[4q][o],...,W2[4q+3][o])
  float  b1[32], b2[32], W3s[32];
  float  xs[NWARP][NP][2];
  float  b3s, scale_s;
};

__device__ __forceinline__ u64 pk2(float a, float b) {
  u64 r; asm("mov.b64 %0, {%1, %2};" : "=l"(r) : "f"(a), "f"(b)); return r;
}
__device__ __forceinline__ void fma2(u64& d, u64 a, u64 b) {
  asm("fma.rn.f32x2 %0, %1, %2, %3;" : "=l"(d) : "l"(a), "l"(b), "l"(d));
}
__device__ __forceinline__ float hdot2(u64 a, u64 b) {
  u64 p; asm("mul.rn.f32x2 %0, %1, %2;" : "=l"(p) : "l"(a), "l"(b));
  float lo, hi; asm("mov.b64 {%0, %1}, %2;" : "=f"(lo), "=f"(hi) : "l"(p));
  return lo + hi;
}
__device__ __forceinline__ float silu_f(float x) {
  float t;
  asm("tanh.approx.f32 %0, %1;" : "=f"(t) : "f"(x * 0.5f));
  return 0.5f * x * (1.0f + t);
}

__global__ void __launch_bounds__(NTHR, 2)
pfaffian_kernel(const float* __restrict__ x, const int* __restrict__ spin,
                const float* __restrict__ F_ud, const float* __restrict__ F_uu,
                const float* __restrict__ F_dd,
                const float* __restrict__ W1, const float* __restrict__ b1,
                const float* __restrict__ W2, const float* __restrict__ b2,
                const float* __restrict__ W3, const float* __restrict__ b3,
                const float* __restrict__ scale,
                float* __restrict__ out, int Bt) {
  extern __shared__ char smem_raw[];
  Smem* S = reinterpret_cast<Smem*>(smem_raw);
  const int tid = threadIdx.x;
  const int w = tid >> 5, lane = tid & 31;

  // ---------- stage static data ----------
  for (int idx = tid; idx < 3 * 32 * 32; idx += NTHR) {
    int m = idx >> 10, r = idx & 1023, k2 = r >> 5, l = r & 31;
    int k = 2 * k2;
    float4 v;
    if (m == 2) {
      v.x = F_ud[k * 64 + l];       v.y = F_ud[k * 64 + l + 32];
      v.z = F_ud[(k + 1) * 64 + l]; v.w = F_ud[(k + 1) * 64 + l + 32];
    } else {
      const float* F = m ? F_dd : F_uu;
      v.x = F[k * 64 + l]            - F[l * 64 + k];
      v.y = F[k * 64 + l + 32]       - F[(l + 32) * 64 + k];
      v.z = F[(k + 1) * 64 + l]      - F[l * 64 + k + 1];
      v.w = F[(k + 1) * 64 + l + 32] - F[(l + 32) * 64 + k + 1];
    }
    S->F4[m][k2][l] = v;
  }
  if (tid < 32) {
    int o = tid;
    S->W1t[o] = make_float4(W1[o], W1[32 + o], W1[64 + o], W1[96 + o]);
    S->b1[o] = b1[o]; S->b2[o] = b2[o]; S->W3s[o] = W3[o];
  }
  for (int idx = tid; idx < 32 * 8; idx += NTHR) {
    int o = idx >> 3, q = idx & 7;
    S->W2t[o][q] = make_float4(W2[(4 * q + 0) * 32 + o], W2[(4 * q + 1) * 32 + o],
                               W2[(4 * q + 2) * 32 + o], W2[(4 * q + 3) * 32 + o]);
  }
  if (tid == 0) { S->b3s = b3[0]; S->scale_s = scale[0]; }
  __syncthreads();

  // ---------- per-lane basis norm constants ----------
  const int nx1 = lane >> 3, nyi = lane & 7;
  float nA = 0.f, nB = 0.f, nC = 0.f;
  {
    double spi = sqrt(M_PI);
    double d = 1.0;
    for (int m2 = 0; m2 < 8; m2++) {
      float v = (float)(1.0 / sqrt(d * spi));
      if (m2 == nx1) nA = v;
      if (m2 == nx1 + 4) nB = v;
      if (m2 == nyi) nC = v;
      d *= 2.0 * (m2 + 1);
    }
  }
  const float norm1 = nA * nC, norm2 = nB * nC;
  const float scl = S->scale_s, b3v = S->b3s;

  const int ngroups = (Bt + NWARP - 1) / NWARP;
  for (int g = blockIdx.x; g < ngroups; g += gridDim.x) {
    const int e = g * NWARP + w;
    if (e >= Bt) continue;

    // ---- load x, spin ----
    int sval = 0;
    if (lane < NP) {
      float2 xv = *reinterpret_cast<const float2*>(x + (size_t)e * NP * 2 + lane * 2);
      S->xs[w][lane][0] = xv.x;
      S->xs[w][lane][1] = xv.y;
      sval = spin[(size_t)e * NP + lane];
    }
    unsigned mask = __ballot_sync(0xffffffffu, (lane < NP) && (sval == 1));
    __syncwarp();

    // ---- basis Phi (scalar into smem) ----
#pragma unroll
    for (int p = 0; p < NP; p++) {
      float u = S->xs[w][p][0], v = S->xs[w][p][1];
      float hm = 1.f, h = 2.f * u;
      float hxa = (nx1 == 0) ? 1.f : h;
      float hxb = h;
#pragma unroll
      for (int k = 2; k < 8; k++) {
        float hn = fmaf(2.f * u, h, -2.f * (float)(k - 1) * hm);
        hm = h; h = hn;
        if (nx1 == k) hxa = hn;
        if (nx1 + 4 == k) hxb = hn;
      }
      float gm = 1.f, gh = 2.f * v;
      float hy = (nyi == 0) ? 1.f : gh;
#pragma unroll
      for (int k = 2; k < 8; k++) {
        float gn = fmaf(2.f * v, gh, -2.f * (float)(k - 1) * gm);
        gm = gh; gh = gn;
        if (nyi == k) hy = gn;
      }
      float gexp = __expf(-0.5f * (u * u + v * v));
      S->phis[w][p][lane]      = hxa * hy * (norm1 * gexp);
      S->phis[w][p][lane + 32] = hxb * hy * (norm2 * gexp);
    }
    __syncwarp();

    // ---- batched k-loop: one F read feeds all 6 particles, packed f32x2 ----
    u64 acc_uu[NP], acc_dd[NP], acc_ud[NP];
#pragma unroll
    for (int p = 0; p < NP; p++) { acc_uu[p] = 0ull; acc_dd[p] = 0ull; acc_ud[p] = 0ull; }

#pragma unroll 4
    for (int kk = 0; kk < 16; kk++) {
      float4 ph[NP];
#pragma unroll
      for (int p = 0; p < NP; p++)
        ph[p] = *reinterpret_cast<const float4*>(&S->phis[w][p][4 * kk]);
#pragma unroll
      for (int h = 0; h < 2; h++) {
        float4 fu = S->F4[0][2 * kk + h][lane];
        float4 fd = S->F4[1][2 * kk + h][lane];
        float4 fx = S->F4[2][2 * kk + h][lane];
        u64 fu_lo = pk2(fu.x, fu.y), fu_hi = pk2(fu.z, fu.w);
        u64 fd_lo = pk2(fd.x, fd.y), fd_hi = pk2(fd.z, fd.w);
        u64 fx_lo = pk2(fx.x, fx.y), fx_hi = pk2(fx.z, fx.w);
#pragma unroll
        for (int p = 0; p < NP; p++) {
          float p0 = h ? ph[p].z : ph[p].x;
          float p1 = h ? ph[p].w : ph[p].y;
          u64 d0 = pk2(p0, p0), d1 = pk2(p1, p1);
          fma2(acc_uu[p], d0, fu_lo); fma2(acc_uu[p], d1, fu_hi);
          fma2(acc_dd[p], d0, fd_lo); fma2(acc_dd[p], d1, fd_hi);
          fma2(acc_ud[p], d0, fx_lo); fma2(acc_ud[p], d1, fx_hi);
        }
      }
    }

    // G_same select + packed phi reload
    u64 Gs[NP], phip[NP];
#pragma unroll
    for (int p = 0; p < NP; p++) {
      Gs[p] = ((mask >> p) & 1) ? acc_dd[p] : acc_uu[p];
      phip[p] = pk2(S->phis[w][p][lane], S->phis[w][p][lane + 32]);
    }

    // ---- A base entries for 15 upper-tri pairs (registers + shfl) ----
    float abase = 0.f;
    {
      constexpr int PIc[15] = {0,0,0,0,0,1,1,1,1,2,2,2,3,3,4};
      constexpr int PJc[15] = {1,2,3,4,5,2,3,4,5,3,4,5,4,5,5};
#pragma unroll
      for (int t = 0; t < 15; t++) {
        const int i = PIc[t], j = PJc[t];
        int si = (mask >> i) & 1, sj = (mask >> j) & 1;
        float ds = hdot2(Gs[i], phip[j]);
        float fv = hdot2(acc_ud[i], phip[j]);
        float rv = hdot2(acc_ud[j], phip[i]);
        float val = (si == sj) ? ds : ((si == 0) ? fv : -rv);
#pragma unroll
        for (int off = 16; off; off >>= 1)
          val += __shfl_xor_sync(0xffffffffu, val, off);
        if (lane == t) abase = val;
      }
    }

    // ---- pair-correction MLP: lanes 0..14 fwd, 16..30 rev ----
    float finalA = 0.f;
    {
      int t = lane & 15;
      bool rev = lane >= 16;
      int pi = (int)((CI_PACK >> (4 * t)) & 15);
      int pj_ = (int)((CJ_PACK >> (4 * t)) & 15);
      int i = rev ? pj_ : pi;
      int j = rev ? pi : pj_;
      float f0 = S->xs[w][i][0] - S->xs[w][j][0];
      float f1 = S->xs[w][i][1] - S->xs[w][j][1];
      float f2v = f0 * f0 + f1 * f1;
      float f3 = (((mask >> i) & 1) == ((mask >> j) & 1)) ? 1.f : 0.f;

      float h1r[32];
#pragma unroll
      for (int o = 0; o < 32; o++) {
        float4 w4 = S->W1t[o];
        float acc = fmaf(f0, w4.x, fmaf(f1, w4.y, fmaf(f2v, w4.z, fmaf(f3, w4.w, S->b1[o]))));
        h1r[o] = silu_f(acc);
      }
      float outv = b3v;
#pragma unroll 4
      for (int o = 0; o < 32; o++) {
        float acc = S->b2[o];
#pragma unroll
        for (int q = 0; q < 8; q++) {
          float4 w4 = S->W2t[o][q];
          acc = fmaf(h1r[4 * q], w4.x,
                fmaf(h1r[4 * q + 1], w4.y,
                fmaf(h1r[4 * q + 2], w4.z,
                fmaf(h1r[4 * q + 3], w4.w, acc))));
        }
        outv = fmaf(silu_f(acc), S->W3s[o], outv);
      }
      float orev = __shfl_down_sync(0xffffffffu, outv, 16);
      finalA = abase + scl * (outv - orev);   // valid on lanes 0..14
    }

    // ---- gather A via shfl, Pfaffian ----
    {
      float a0  = __shfl_sync(0xffffffffu, finalA, 0);
      float a1  = __shfl_sync(0xffffffffu, finalA, 1);
      float a2  = __shfl_sync(0xffffffffu, finalA, 2);
      float a3  = __shfl_sync(0xffffffffu, finalA, 3);
      float a4  = __shfl_sync(0xffffffffu, finalA, 4);
      float a5  = __shfl_sync(0xffffffffu, finalA, 5);
      float a6  = __shfl_sync(0xffffffffu, finalA, 6);
      float a7  = __shfl_sync(0xffffffffu, finalA, 7);
      float a8  = __shfl_sync(0xffffffffu, finalA, 8);
      float a9  = __shfl_sync(0xffffffffu, finalA, 9);
      float a10 = __shfl_sync(0xffffffffu, finalA, 10);
      float a11 = __shfl_sync(0xffffffffu, finalA, 11);
      float a12 = __shfl_sync(0xffffffffu, finalA, 12);
      float a13 = __shfl_sync(0xffffffffu, finalA, 13);
      float a14 = __shfl_sync(0xffffffffu, finalA, 14);
      if (lane == 0) {
        float pf = a0 * (a9 * a14 - a10 * a13 + a11 * a12)
                 - a1 * (a6 * a14 - a7 * a13 + a8 * a12)
                 + a2 * (a5 * a14 - a7 * a11 + a8 * a10)
                 - a3 * (a5 * a13 - a6 * a11 + a8 * a9)
                 + a4 * (a5 * a12 - a6 * a10 + a7 * a9);
        float sgn = (pf == 0.f) ? 1.f : ((pf > 0.f) ? 1.f : -1.f);
        float la = 0.5f * __logf(pf * pf);
        out[e] = sgn;
        out[Bt + e] = la;
      }
    }
    __syncwarp();
  }
}

}  // namespace

extern "C" void kernel_launch(void* const* d_in, const int* in_sizes, int n_in,
                              void* d_out, int out_size) {
  const float* x     = (const float*)d_in[0];
  const int*   spin  = (const int*)d_in[1];
  const float* F_ud  = (const float*)d_in[2];
  const float* F_uu  = (const float*)d_in[3];
  const float* F_dd  = (const float*)d_in[4];
  const float* W1    = (const float*)d_in[5];
  const float* b1    = (const float*)d_in[6];
  const float* W2    = (const float*)d_in[7];
  const float* b2    = (const float*)d_in[8];
  const float* W3    = (const float*)d_in[9];
  const float* b3    = (const float*)d_in[10];
  const float* scale = (const float*)d_in[11];
  float* out = (float*)d_out;

  const int Bt = in_sizes[0] / (NP * 2);
  const int smem = (int)sizeof(Smem);

  cudaFuncSetAttribute(pfaffian_kernel, cudaFuncAttributeMaxDynamicSharedMemorySize, smem);

  int dev = 0;
  cudaGetDevice(&dev);
  int nsm = 148;
  cudaDeviceGetAttribute(&nsm, cudaDevAttrMultiProcessorCount, dev);

  const int ngroups = (Bt + NWARP - 1) / NWARP;
  int grid = nsm * 2;
  if (grid > ngroups) grid = ngroups;

  pfaffian_kernel<<<grid, NTHR, smem>>>(x, spin, F_ud, F_uu, F_dd,
                                        W1, b1, W2, b2, W3, b3, scale, out, Bt);
}